// round 15
// baseline (speedup 1.0000x reference)
#include <cuda_runtime.h>
#include <math.h>
#include <stdint.h>

#define G   16
#define C   256
#define NP  5
#define NN  4096   // 64*64
#define H   1024
#define W   1024
#define STAGES 10

// ---------------- scratch (device globals; no allocations allowed) ----------
__device__ float g_msmall[G][NN];
__device__ float g_munum[G][C][NP];       // mu numerator (pre-l2norm)
__device__ float g_z[G][NP][NN];          // softmax z, k-planar
__device__ float g_sim[G][NP][NN];        // final similarity maps
__device__ float g_csum_part[G][16][NP];  // colsum partials (fixed order)
__device__ unsigned long long g_best[G][NP];
__device__ int g_visible[G];

// ---------------- helpers ---------------------------------------------------
__device__ __forceinline__ unsigned long long pack_key(float v, unsigned idx) {
    unsigned u = __float_as_uint(v);
    u = (u & 0x80000000u) ? ~u : (u | 0x80000000u);   // order-preserving
    return (((unsigned long long)u) << 32) | (0xFFFFFFFFu - idx);
}

// ---------------- m_small (exact: frac = 0.5 both dims, values k/4) ---------
__global__ __launch_bounds__(256)
void k_msmall(const int* __restrict__ fg) {
    int b = blockIdx.x;
    int g = b >> 4;
    int n = ((b & 15) << 8) + threadIdx.x;
    int y = n >> 6, x = n & 63;
    const int* p = fg + ((size_t)g * H + (y * 16 + 7)) * W + (x * 16 + 7);
    int s = (p[0] != 0) + (p[1] != 0) + (p[W] != 0) + (p[W + 1] != 0);
    g_msmall[g][n] = 0.25f * (float)s;
}

// ---------------- init: munum = raw mu (normalization fused into k_logits) --
__global__ __launch_bounds__(256)
void k_init(const float* __restrict__ mu_in) {
    int c = threadIdx.x;
#pragma unroll
    for (int k = 0; k < NP; k++) {
        float v = mu_in[c * NP + k];
        for (int g = 0; g < G; g++) g_munum[g][c][k] = v;
    }
    if (c < G * NP) ((unsigned long long*)g_best)[c] = 0ull;
    if (c < G) g_visible[c] = 0;
}

// ---------------- logits: [l2norm prologue] ; a = x^T mu ; softmax ; z ------
// grid = G*16 x 256; one n per thread. simmode: writes sim instead.
// NOTE: colsum partial pattern (1 n per lane, 8-warp tree, 16 blocks/g) is
// value-critical and frozen.
__global__ __launch_bounds__(256)
void k_logits(const float* __restrict__ feat, int simmode) {
    int b = blockIdx.x;
    int g = b >> 4;
    int n = ((b & 15) << 8) + threadIdx.x;

    __shared__ __align__(16) float smu[C * NP];
    __shared__ float rnorm[NP];
    {
        const float* mun = (const float*)g_munum[g];
        for (int i = threadIdx.x; i < C * NP; i += 256) smu[i] = mun[i];
    }
    __syncthreads();
    if (threadIdx.x < NP) {
        float s2 = 0.0f;
        for (int cc = 0; cc < C; cc++) {
            float v = smu[cc * NP + threadIdx.x];
            s2 = __fadd_rn(s2, __fmul_rn(v, v));
        }
        rnorm[threadIdx.x] = __fadd_rn(1e-6f, sqrtf(s2));
    }
    __syncthreads();
    for (int i = threadIdx.x; i < C * NP; i += 256)
        smu[i] = __fdiv_rn(smu[i], rnorm[i % NP]);
    __syncthreads();

    float ms = g_msmall[g][n];
    float a[NP];
#pragma unroll
    for (int k = 0; k < NP; k++) a[k] = 0.0f;

    const float* fb = feat + n;
#pragma unroll 8
    for (int c = 0; c < C; c++) {                       // ascending c
        float x = __fmul_rn(ms, fb[(size_t)c * NN]);    // materialized x element
        const float* m = &smu[c * NP];
#pragma unroll
        for (int k = 0; k < NP; k++) a[k] = __fmaf_rn(x, m[k], a[k]);
    }

    if (simmode) {
#pragma unroll
        for (int k = 0; k < NP; k++) g_sim[g][k][n] = a[k];
        return;
    }

    float s[NP];
#pragma unroll
    for (int k = 0; k < NP; k++) s[k] = __fmul_rn(20.0f, a[k]);
    float mx = s[0];
#pragma unroll
    for (int k = 1; k < NP; k++) mx = fmaxf(mx, s[k]);
    float e[NP];
#pragma unroll
    for (int k = 0; k < NP; k++) e[k] = expf(__fadd_rn(s[k], -mx));
    float sum = e[0];
#pragma unroll
    for (int k = 1; k < NP; k++) sum = __fadd_rn(sum, e[k]);

    float zs[NP];
#pragma unroll
    for (int k = 0; k < NP; k++) {
        float z = __fdiv_rn(e[k], sum);                 // e / sum (IEEE divide)
        g_z[g][k][n] = z;
        zs[k] = z;
    }

    // deterministic colsum partials: shfl tree -> fixed 8-warp sum
    __shared__ float wpart[8][NP];
    int warp = threadIdx.x >> 5, lane = threadIdx.x & 31;
#pragma unroll
    for (int k = 0; k < NP; k++) {
        float t = zs[k];
        for (int o = 16; o > 0; o >>= 1) t += __shfl_down_sync(0xffffffffu, t, o);
        if (lane == 0) wpart[warp][k] = t;
    }
    __syncthreads();
    if (threadIdx.x < NP) {
        float ssum = 0.0f;
#pragma unroll
        for (int w = 0; w < 8; w++) ssum = __fadd_rn(ssum, wpart[w][threadIdx.x]);
        g_csum_part[g][b & 15][threadIdx.x] = ssum;
    }
}

// ---------------- mu numerator: 16 warps x 1 channel, fused zn staging ------
// grid = G*16 x 512 (16 warps x 1 channel = 16 channels/block; 16 blocks/g).
// Per-(c,k) FMA chain: n = t*2048 + it*128 + lane*4 ascending, groups of
// 4 FMAs in (x0,x1,x2,x3) order -> byte-identical to R7..R14 chains.
// zn = __fdiv_rn(z, den) computed during staging (same values as old k_zn);
// den = fixed-order 16-partial sum + 1e-6 (redundant per thread, identical).
__global__ __launch_bounds__(512)
void k_mu(const float* __restrict__ feat) {
    int b = blockIdx.x;
    int g = b >> 4;
    int warp = threadIdx.x >> 5, lane = threadIdx.x & 31;
    int c = ((b & 15) << 4) + warp;                 // one channel per warp

    __shared__ __align__(16) float zns[NP][2048];   // 40 KB
    __shared__ __align__(16) float msl[2048];       //  8 KB  (total 48 KB)

    float den[NP];
#pragma unroll
    for (int k = 0; k < NP; k++) {
        float s = 0.0f;
#pragma unroll
        for (int j = 0; j < 16; j++) s = __fadd_rn(s, g_csum_part[g][j][k]);
        den[k] = __fadd_rn(1e-6f, s);
    }

    float acc[NP];
#pragma unroll
    for (int k = 0; k < NP; k++) acc[k] = 0.0f;

    const float* fr = feat + (size_t)c * NN;

    for (int t = 0; t < 2; t++) {
        if (t) __syncthreads();                     // previous tile consumed
        // stage ms (bit-copy) + zn (divide once, same values as old k_zn)
        for (int i = threadIdx.x; i < 512; i += 512)
            ((float4*)msl)[i] = __ldg((const float4*)(g_msmall[g] + t * 2048) + i);
        for (int i = threadIdx.x; i < NP * 512; i += 512) {
            int k = i >> 9, nn = i & 511;
            float4 zv = __ldg((const float4*)(g_z[g][k] + t * 2048) + nn);
            float4 o;
            o.x = __fdiv_rn(zv.x, den[k]);
            o.y = __fdiv_rn(zv.y, den[k]);
            o.z = __fdiv_rn(zv.z, den[k]);
            o.w = __fdiv_rn(zv.w, den[k]);
            ((float4*)zns[k])[nn] = o;
        }
        __syncthreads();

#pragma unroll 4
        for (int it = 0; it < 16; it++) {
            int nn = it * 128 + lane * 4;
            float4 f4 = __ldg((const float4*)(fr + t * 2048 + nn));
            float4 m4 = *(const float4*)&msl[nn];
            float x0 = __fmul_rn(m4.x, f4.x);
            float x1 = __fmul_rn(m4.y, f4.y);
            float x2 = __fmul_rn(m4.z, f4.z);
            float x3 = __fmul_rn(m4.w, f4.w);
#pragma unroll
            for (int k = 0; k < NP; k++) {
                float4 z4 = *(const float4*)&zns[k][nn];
                acc[k] = __fmaf_rn(x0, z4.x, acc[k]);
                acc[k] = __fmaf_rn(x1, z4.y, acc[k]);
                acc[k] = __fmaf_rn(x2, z4.z, acc[k]);
                acc[k] = __fmaf_rn(x3, z4.w, acc[k]);
            }
        }
    }

    // identical 32-lane shuffle tree per (c,k)
#pragma unroll
    for (int k = 0; k < NP; k++)
        for (int o = 16; o > 0; o >>= 1)
            acc[k] += __shfl_down_sync(0xffffffffu, acc[k], o);

    if (lane == 0) {
#pragma unroll
        for (int k = 0; k < NP; k++) g_munum[g][c][k] = acc[k];
    }
}

// ---------------- final: upsample + assign + write + reductions -------------
__global__ __launch_bounds__(256)
void k_final(const int* __restrict__ fg, float* __restrict__ out) {
    int y = blockIdx.x, g = blockIdx.y;

    __shared__ float row[NP][64];
    float sy = (y + 0.5f) * 0.0625f - 0.5f;          // exact in f32
    sy = fminf(fmaxf(sy, 0.0f), 63.0f);
    int y0 = (int)sy; int y1 = min(y0 + 1, 63); float fy = sy - (float)y0;
    float wy0 = 1.0f - fy;

    for (int i = threadIdx.x; i < NP * 64; i += 256) {
        int k = i >> 6, xs = i & 63;
        float a = g_sim[g][k][y0 * 64 + xs];
        float bb = g_sim[g][k][y1 * 64 + xs];
        row[k][xs] = __fadd_rn(__fmul_rn(a, wy0), __fmul_rn(bb, fy));
    }
    __syncthreads();

    int xb = threadIdx.x << 2;
    int4 fg4 = *(const int4*)(fg + ((size_t)g * H + y) * W + xb);
    const int* fgv4 = &fg4.x;

    unsigned long long best[NP];
#pragma unroll
    for (int k = 0; k < NP; k++) best[k] = 0ull;
    int vb = 0;
    float ov[NP][4];

#pragma unroll
    for (int j = 0; j < 4; j++) {
        int x = xb + j;
        float sx = (x + 0.5f) * 0.0625f - 0.5f;
        sx = fminf(fmaxf(sx, 0.0f), 63.0f);
        int x0 = (int)sx; int x1 = min(x0 + 1, 63); float fx = sx - (float)x0;
        float wx0 = 1.0f - fx;

        float v[NP];
#pragma unroll
        for (int k = 0; k < NP; k++)
            v[k] = __fadd_rn(__fmul_rn(row[k][x0], wx0), __fmul_rn(row[k][x1], fx));

        int bk = 0; float bv = v[0];
#pragma unroll
        for (int k = 1; k < NP; k++) if (v[k] > bv) { bv = v[k]; bk = k; }

        int isfg = (fgv4[j] != 0);
        unsigned idx = (unsigned)(y * W + x);
#pragma unroll
        for (int k = 0; k < NP; k++) {
            float o = (isfg && k == bk) ? v[k] : 0.0f;
            ov[k][j] = o;
            unsigned long long key = pack_key(o, idx);
            if (key > best[k]) best[k] = key;
        }
        if (isfg) vb |= (1 << bk);
    }

#pragma unroll
    for (int k = 0; k < NP; k++) {
        float4 w4 = make_float4(ov[k][0], ov[k][1], ov[k][2], ov[k][3]);
        *(float4*)(out + ((((size_t)g * NP + k) * H + y) * W + xb)) = w4;
    }

#pragma unroll
    for (int k = 0; k < NP; k++)
        for (int o = 16; o > 0; o >>= 1) {
            unsigned long long other = __shfl_down_sync(0xffffffffu, best[k], o);
            if (other > best[k]) best[k] = other;
        }
    for (int o = 16; o > 0; o >>= 1) vb |= __shfl_down_sync(0xffffffffu, vb, o);

    __shared__ unsigned long long sb[8][NP];
    __shared__ int sv[8];
    int warp = threadIdx.x >> 5, lane = threadIdx.x & 31;
    if (lane == 0) {
#pragma unroll
        for (int k = 0; k < NP; k++) sb[warp][k] = best[k];
        sv[warp] = vb;
    }
    __syncthreads();
    if (threadIdx.x < NP) {
        int k = threadIdx.x;
        unsigned long long m = sb[0][k];
#pragma unroll
        for (int w = 1; w < 8; w++) if (sb[w][k] > m) m = sb[w][k];
        atomicMax(&g_best[g][k], m);
    }
    if (threadIdx.x == 0) {
        int o = 0;
#pragma unroll
        for (int w = 0; w < 8; w++) o |= sv[w];
        atomicOr(&g_visible[g], o);
    }
}

// ---------------- epilogue --------------------------------------------------
__global__ __launch_bounds__(128)
void k_points(float* __restrict__ out) {
    int t = threadIdx.x;
    if (t >= G * NP) return;
    int g = t / NP, k = t % NP;
    int vis = (g_visible[g] >> k) & 1;
    unsigned idx = 0xFFFFFFFFu - (unsigned)(g_best[g][k] & 0xFFFFFFFFull);
    float px = (float)(idx & (W - 1));
    float py = (float)(idx >> 10);
    size_t P = (size_t)G * NP * H * W;
    out[P + t * 2]     = vis ? px : -0.001f;
    out[P + t * 2 + 1] = vis ? py : -0.001f;
    out[P + (size_t)G * NP * 2 + t] = (float)vis;
}

// ---------------- launch ----------------------------------------------------
extern "C" void kernel_launch(void* const* d_in, const int* in_sizes, int n_in,
                              void* d_out, int out_size) {
    const float* feature = (const float*)d_in[0];   // (256,64,64)
    const int*   fg_mask = (const int*)d_in[1];     // (16,1024,1024)
    // d_in[2] = bboxes (unused by reference)
    const float* mu_in   = (const float*)d_in[3];   // (1,256,5)
    float* out = (float*)d_out;

    k_msmall<<<G * 16, 256>>>(fg_mask);
    k_init<<<1, 256>>>(mu_in);

    for (int it = 0; it < STAGES; it++) {
        k_logits<<<G * 16, 256>>>(feature, 0);
        k_mu<<<G * 16, 512>>>(feature);
    }
    k_logits<<<G * 16, 256>>>(feature, 1);   // sim = x^T mu_final

    k_final<<<dim3(H, G), 256>>>(fg_mask, out);
    k_points<<<1, 128>>>(out);
}

// round 16
// speedup vs baseline: 1.0109x; 1.0109x over previous
#include <cuda_runtime.h>
#include <math.h>
#include <stdint.h>

#define G   16
#define C   256
#define NP  5
#define NN  4096   // 64*64
#define H   1024
#define W   1024
#define STAGES 10

// ---------------- scratch (device globals; no allocations allowed) ----------
__device__ float g_msmall[G][NN];
__device__ float g_munum[G][C][NP];       // mu numerator (pre-l2norm)
__device__ float g_z[G][NP][NN];          // softmax z, k-planar
__device__ float g_sim[G][NP][NN];        // final similarity maps
__device__ float g_csum_part[G][16][NP];  // colsum partials (fixed order)
__device__ unsigned long long g_best[G][NP];
__device__ int g_visible[G];

// ---------------- helpers ---------------------------------------------------
__device__ __forceinline__ unsigned long long pack_key(float v, unsigned idx) {
    unsigned u = __float_as_uint(v);
    u = (u & 0x80000000u) ? ~u : (u | 0x80000000u);   // order-preserving
    return (((unsigned long long)u) << 32) | (0xFFFFFFFFu - idx);
}

// ---------------- m_small (exact: frac = 0.5 both dims, values k/4) ---------
__global__ __launch_bounds__(256)
void k_msmall(const int* __restrict__ fg) {
    int b = blockIdx.x;
    int g = b >> 4;
    int n = ((b & 15) << 8) + threadIdx.x;
    int y = n >> 6, x = n & 63;
    const int* p = fg + ((size_t)g * H + (y * 16 + 7)) * W + (x * 16 + 7);
    int s = (p[0] != 0) + (p[1] != 0) + (p[W] != 0) + (p[W + 1] != 0);
    g_msmall[g][n] = 0.25f * (float)s;
}

// ---------------- init: munum = raw mu (normalization fused into k_logits) --
__global__ __launch_bounds__(256)
void k_init(const float* __restrict__ mu_in) {
    int c = threadIdx.x;
#pragma unroll
    for (int k = 0; k < NP; k++) {
        float v = mu_in[c * NP + k];
        for (int g = 0; g < G; g++) g_munum[g][c][k] = v;
    }
    if (c < G * NP) ((unsigned long long*)g_best)[c] = 0ull;
    if (c < G) g_visible[c] = 0;
}

// ---------------- logits: [l2norm prologue] ; a = x^T mu ; softmax ; z ------
// grid = G*16 x 256; one n per thread. simmode: writes sim instead.
// NOTE: colsum partial pattern (1 n per lane, 8-warp tree, 16 blocks/g) is
// value-critical and frozen.
__global__ __launch_bounds__(256)
void k_logits(const float* __restrict__ feat, int simmode) {
    int b = blockIdx.x;
    int g = b >> 4;
    int n = ((b & 15) << 8) + threadIdx.x;

    __shared__ __align__(16) float smu[C * NP];
    __shared__ float rnorm[NP];
    {
        const float* mun = (const float*)g_munum[g];
        for (int i = threadIdx.x; i < C * NP; i += 256) smu[i] = mun[i];
    }
    __syncthreads();
    if (threadIdx.x < NP) {
        float s2 = 0.0f;
        for (int cc = 0; cc < C; cc++) {
            float v = smu[cc * NP + threadIdx.x];
            s2 = __fadd_rn(s2, __fmul_rn(v, v));
        }
        rnorm[threadIdx.x] = __fadd_rn(1e-6f, sqrtf(s2));
    }
    __syncthreads();
    for (int i = threadIdx.x; i < C * NP; i += 256)
        smu[i] = __fdiv_rn(smu[i], rnorm[i % NP]);
    __syncthreads();

    float ms = g_msmall[g][n];
    float a[NP];
#pragma unroll
    for (int k = 0; k < NP; k++) a[k] = 0.0f;

    const float* fb = feat + n;
#pragma unroll 8
    for (int c = 0; c < C; c++) {                       // ascending c
        float x = __fmul_rn(ms, fb[(size_t)c * NN]);    // materialized x element
        const float* m = &smu[c * NP];
#pragma unroll
        for (int k = 0; k < NP; k++) a[k] = __fmaf_rn(x, m[k], a[k]);
    }

    if (simmode) {
#pragma unroll
        for (int k = 0; k < NP; k++) g_sim[g][k][n] = a[k];
        return;
    }

    float s[NP];
#pragma unroll
    for (int k = 0; k < NP; k++) s[k] = __fmul_rn(20.0f, a[k]);
    float mx = s[0];
#pragma unroll
    for (int k = 1; k < NP; k++) mx = fmaxf(mx, s[k]);
    float e[NP];
#pragma unroll
    for (int k = 0; k < NP; k++) e[k] = expf(__fadd_rn(s[k], -mx));
    float sum = e[0];
#pragma unroll
    for (int k = 1; k < NP; k++) sum = __fadd_rn(sum, e[k]);

    float zs[NP];
#pragma unroll
    for (int k = 0; k < NP; k++) {
        float z = __fdiv_rn(e[k], sum);                 // e / sum (IEEE divide)
        g_z[g][k][n] = z;
        zs[k] = z;
    }

    // deterministic colsum partials: shfl tree -> fixed 8-warp sum
    __shared__ float wpart[8][NP];
    int warp = threadIdx.x >> 5, lane = threadIdx.x & 31;
#pragma unroll
    for (int k = 0; k < NP; k++) {
        float t = zs[k];
        for (int o = 16; o > 0; o >>= 1) t += __shfl_down_sync(0xffffffffu, t, o);
        if (lane == 0) wpart[warp][k] = t;
    }
    __syncthreads();
    if (threadIdx.x < NP) {
        float ssum = 0.0f;
#pragma unroll
        for (int w = 0; w < 8; w++) ssum = __fadd_rn(ssum, wpart[w][threadIdx.x]);
        g_csum_part[g][b & 15][threadIdx.x] = ssum;
    }
}

// ---------------- mu numerator: 8 warps x 2 channels, 256 blocks ------------
// grid = G*16 x 256 (8 warps x 2 channels = 16 channels/block; 16 blocks/g).
// All 148 SMs active (256 blocks), 2 blocks/SM, LDS amortized over 2 channels.
// Per-(c,k) FMA chain: n = t*2048 + it*128 + lane*4 ascending, groups of
// 4 FMAs in (x0,x1,x2,x3) order -> byte-identical to R7..R15 chains.
// zn = __fdiv_rn(z, den) computed during staging (same values as old k_zn);
// den = fixed-order 16-partial sum + 1e-6 (redundant per thread, identical).
__global__ __launch_bounds__(256)
void k_mu(const float* __restrict__ feat) {
    int b = blockIdx.x;
    int g = b >> 4;
    int warp = threadIdx.x >> 5, lane = threadIdx.x & 31;
    int c0 = ((b & 15) << 4) + (warp << 1);         // 2 channels c0, c0+1

    __shared__ __align__(16) float zns[NP][2048];   // 40 KB
    __shared__ __align__(16) float msl[2048];       //  8 KB  (total 48 KB)

    float den[NP];
#pragma unroll
    for (int k = 0; k < NP; k++) {
        float s = 0.0f;
#pragma unroll
        for (int j = 0; j < 16; j++) s = __fadd_rn(s, g_csum_part[g][j][k]);
        den[k] = __fadd_rn(1e-6f, s);
    }

    float acc[2][NP];
#pragma unroll
    for (int cc = 0; cc < 2; cc++)
#pragma unroll
        for (int k = 0; k < NP; k++) acc[cc][k] = 0.0f;

    for (int t = 0; t < 2; t++) {
        if (t) __syncthreads();                     // previous tile consumed
        // stage ms (bit-copy) + zn (divide once, same values as old k_zn)
        for (int i = threadIdx.x; i < 512; i += 256)
            ((float4*)msl)[i] = __ldg((const float4*)(g_msmall[g] + t * 2048) + i);
        for (int i = threadIdx.x; i < NP * 512; i += 256) {
            int k = i >> 9, nn = i & 511;
            float4 zv = __ldg((const float4*)(g_z[g][k] + t * 2048) + nn);
            float4 o;
            o.x = __fdiv_rn(zv.x, den[k]);
            o.y = __fdiv_rn(zv.y, den[k]);
            o.z = __fdiv_rn(zv.z, den[k]);
            o.w = __fdiv_rn(zv.w, den[k]);
            ((float4*)zns[k])[nn] = o;
        }
        __syncthreads();

#pragma unroll 2
        for (int it = 0; it < 16; it++) {
            int nn = it * 128 + lane * 4;
            float4 m4 = *(const float4*)&msl[nn];
            float4 z4[NP];
#pragma unroll
            for (int k = 0; k < NP; k++) z4[k] = *(const float4*)&zns[k][nn];
#pragma unroll
            for (int cc = 0; cc < 2; cc++) {
                float4 f4 = __ldg((const float4*)(feat + (size_t)(c0 + cc) * NN
                                                  + t * 2048 + nn));
                float x0 = __fmul_rn(m4.x, f4.x);
                float x1 = __fmul_rn(m4.y, f4.y);
                float x2 = __fmul_rn(m4.z, f4.z);
                float x3 = __fmul_rn(m4.w, f4.w);
#pragma unroll
                for (int k = 0; k < NP; k++) {
                    acc[cc][k] = __fmaf_rn(x0, z4[k].x, acc[cc][k]);
                    acc[cc][k] = __fmaf_rn(x1, z4[k].y, acc[cc][k]);
                    acc[cc][k] = __fmaf_rn(x2, z4[k].z, acc[cc][k]);
                    acc[cc][k] = __fmaf_rn(x3, z4[k].w, acc[cc][k]);
                }
            }
        }
    }

    // identical 32-lane shuffle tree per (c,k)
#pragma unroll
    for (int cc = 0; cc < 2; cc++)
#pragma unroll
        for (int k = 0; k < NP; k++)
            for (int o = 16; o > 0; o >>= 1)
                acc[cc][k] += __shfl_down_sync(0xffffffffu, acc[cc][k], o);

    if (lane == 0) {
#pragma unroll
        for (int cc = 0; cc < 2; cc++)
#pragma unroll
            for (int k = 0; k < NP; k++)
                g_munum[g][c0 + cc][k] = acc[cc][k];
    }
}

// ---------------- final: upsample + assign + write + reductions -------------
__global__ __launch_bounds__(256)
void k_final(const int* __restrict__ fg, float* __restrict__ out) {
    int y = blockIdx.x, g = blockIdx.y;

    __shared__ float row[NP][64];
    float sy = (y + 0.5f) * 0.0625f - 0.5f;          // exact in f32
    sy = fminf(fmaxf(sy, 0.0f), 63.0f);
    int y0 = (int)sy; int y1 = min(y0 + 1, 63); float fy = sy - (float)y0;
    float wy0 = 1.0f - fy;

    for (int i = threadIdx.x; i < NP * 64; i += 256) {
        int k = i >> 6, xs = i & 63;
        float a = g_sim[g][k][y0 * 64 + xs];
        float bb = g_sim[g][k][y1 * 64 + xs];
        row[k][xs] = __fadd_rn(__fmul_rn(a, wy0), __fmul_rn(bb, fy));
    }
    __syncthreads();

    int xb = threadIdx.x << 2;
    int4 fg4 = *(const int4*)(fg + ((size_t)g * H + y) * W + xb);
    const int* fgv4 = &fg4.x;

    unsigned long long best[NP];
#pragma unroll
    for (int k = 0; k < NP; k++) best[k] = 0ull;
    int vb = 0;
    float ov[NP][4];

#pragma unroll
    for (int j = 0; j < 4; j++) {
        int x = xb + j;
        float sx = (x + 0.5f) * 0.0625f - 0.5f;
        sx = fminf(fmaxf(sx, 0.0f), 63.0f);
        int x0 = (int)sx; int x1 = min(x0 + 1, 63); float fx = sx - (float)x0;
        float wx0 = 1.0f - fx;

        float v[NP];
#pragma unroll
        for (int k = 0; k < NP; k++)
            v[k] = __fadd_rn(__fmul_rn(row[k][x0], wx0), __fmul_rn(row[k][x1], fx));

        int bk = 0; float bv = v[0];
#pragma unroll
        for (int k = 1; k < NP; k++) if (v[k] > bv) { bv = v[k]; bk = k; }

        int isfg = (fgv4[j] != 0);
        unsigned idx = (unsigned)(y * W + x);
#pragma unroll
        for (int k = 0; k < NP; k++) {
            float o = (isfg && k == bk) ? v[k] : 0.0f;
            ov[k][j] = o;
            unsigned long long key = pack_key(o, idx);
            if (key > best[k]) best[k] = key;
        }
        if (isfg) vb |= (1 << bk);
    }

#pragma unroll
    for (int k = 0; k < NP; k++) {
        float4 w4 = make_float4(ov[k][0], ov[k][1], ov[k][2], ov[k][3]);
        *(float4*)(out + ((((size_t)g * NP + k) * H + y) * W + xb)) = w4;
    }

#pragma unroll
    for (int k = 0; k < NP; k++)
        for (int o = 16; o > 0; o >>= 1) {
            unsigned long long other = __shfl_down_sync(0xffffffffu, best[k], o);
            if (other > best[k]) best[k] = other;
        }
    for (int o = 16; o > 0; o >>= 1) vb |= __shfl_down_sync(0xffffffffu, vb, o);

    __shared__ unsigned long long sb[8][NP];
    __shared__ int sv[8];
    int warp = threadIdx.x >> 5, lane = threadIdx.x & 31;
    if (lane == 0) {
#pragma unroll
        for (int k = 0; k < NP; k++) sb[warp][k] = best[k];
        sv[warp] = vb;
    }
    __syncthreads();
    if (threadIdx.x < NP) {
        int k = threadIdx.x;
        unsigned long long m = sb[0][k];
#pragma unroll
        for (int w = 1; w < 8; w++) if (sb[w][k] > m) m = sb[w][k];
        atomicMax(&g_best[g][k], m);
    }
    if (threadIdx.x == 0) {
        int o = 0;
#pragma unroll
        for (int w = 0; w < 8; w++) o |= sv[w];
        atomicOr(&g_visible[g], o);
    }
}

// ---------------- epilogue --------------------------------------------------
__global__ __launch_bounds__(128)
void k_points(float* __restrict__ out) {
    int t = threadIdx.x;
    if (t >= G * NP) return;
    int g = t / NP, k = t % NP;
    int vis = (g_visible[g] >> k) & 1;
    unsigned idx = 0xFFFFFFFFu - (unsigned)(g_best[g][k] & 0xFFFFFFFFull);
    float px = (float)(idx & (W - 1));
    float py = (float)(idx >> 10);
    size_t P = (size_t)G * NP * H * W;
    out[P + t * 2]     = vis ? px : -0.001f;
    out[P + t * 2 + 1] = vis ? py : -0.001f;
    out[P + (size_t)G * NP * 2 + t] = (float)vis;
}

// ---------------- launch ----------------------------------------------------
extern "C" void kernel_launch(void* const* d_in, const int* in_sizes, int n_in,
                              void* d_out, int out_size) {
    const float* feature = (const float*)d_in[0];   // (256,64,64)
    const int*   fg_mask = (const int*)d_in[1];     // (16,1024,1024)
    // d_in[2] = bboxes (unused by reference)
    const float* mu_in   = (const float*)d_in[3];   // (1,256,5)
    float* out = (float*)d_out;

    k_msmall<<<G * 16, 256>>>(fg_mask);
    k_init<<<1, 256>>>(mu_in);

    for (int it = 0; it < STAGES; it++) {
        k_logits<<<G * 16, 256>>>(feature, 0);
        k_mu<<<G * 16, 256>>>(feature);
    }
    k_logits<<<G * 16, 256>>>(feature, 1);   // sim = x^T mu_final

    k_final<<<dim3(H, G), 256>>>(fg_mask, out);
    k_points<<<1, 128>>>(out);
}

// round 17
// speedup vs baseline: 1.1256x; 1.1134x over previous
#include <cuda_runtime.h>
#include <math.h>
#include <stdint.h>

#define G   16
#define C   256
#define NP  5
#define NN  4096   // 64*64
#define H   1024
#define W   1024
#define STAGES 10

// ---------------- scratch (device globals; no allocations allowed) ----------
__device__ float g_msmall[G][NN];
__device__ float g_munum[G][C][NP];       // mu numerator (pre-l2norm)
__device__ float g_z[G][NP][NN];          // softmax z, k-planar
__device__ float g_sim[G][NP][NN];        // final similarity maps
__device__ float g_csum_part[G][16][NP];  // colsum partials (fixed order)
__device__ unsigned long long g_best[G][NP];
__device__ int g_visible[G];

// ---------------- helpers ---------------------------------------------------
__device__ __forceinline__ unsigned long long pack_key(float v, unsigned idx) {
    unsigned u = __float_as_uint(v);
    u = (u & 0x80000000u) ? ~u : (u | 0x80000000u);   // order-preserving
    return (((unsigned long long)u) << 32) | (0xFFFFFFFFu - idx);
}

// ---------------- m_small (exact: frac = 0.5 both dims, values k/4) ---------
__global__ __launch_bounds__(256)
void k_msmall(const int* __restrict__ fg) {
    int b = blockIdx.x;
    int g = b >> 4;
    int n = ((b & 15) << 8) + threadIdx.x;
    int y = n >> 6, x = n & 63;
    const int* p = fg + ((size_t)g * H + (y * 16 + 7)) * W + (x * 16 + 7);
    int s = (p[0] != 0) + (p[1] != 0) + (p[W] != 0) + (p[W + 1] != 0);
    g_msmall[g][n] = 0.25f * (float)s;
}

// ---------------- init: munum = raw mu (normalization fused into k_logits) --
__global__ __launch_bounds__(256)
void k_init(const float* __restrict__ mu_in) {
    int c = threadIdx.x;
#pragma unroll
    for (int k = 0; k < NP; k++) {
        float v = mu_in[c * NP + k];
        for (int g = 0; g < G; g++) g_munum[g][c][k] = v;
    }
    if (c < G * NP) ((unsigned long long*)g_best)[c] = 0ull;
    if (c < G) g_visible[c] = 0;
}

// ---------------- logits: [l2norm prologue] ; a = x^T mu ; softmax ; z ------
// grid = G*16 x 256; one n per thread. simmode: writes sim instead.
// mu staged in smem PADDED to 8 floats/channel -> vectorized LDS (layout-only
// change; same float values feed the same ascending-k FMA chain).
// NOTE: colsum partial pattern (1 n per lane, 8-warp tree, 16 blocks/g) is
// value-critical and frozen.
__global__ __launch_bounds__(256)
void k_logits(const float* __restrict__ feat, int simmode) {
    int b = blockIdx.x;
    int g = b >> 4;
    int n = ((b & 15) << 8) + threadIdx.x;

    __shared__ __align__(16) float smu8[C * 8];     // padded: 8 floats per c
    __shared__ float rnorm[NP];
    {
        const float* mun = (const float*)g_munum[g];
        for (int i = threadIdx.x; i < C * NP; i += 256) {
            int cc = i / NP, k = i - cc * NP;
            smu8[cc * 8 + k] = mun[i];
        }
    }
    __syncthreads();
    if (threadIdx.x < NP) {
        float s2 = 0.0f;
        for (int cc = 0; cc < C; cc++) {            // sequential ascending c
            float v = smu8[cc * 8 + threadIdx.x];
            s2 = __fadd_rn(s2, __fmul_rn(v, v));
        }
        rnorm[threadIdx.x] = __fadd_rn(1e-6f, sqrtf(s2));
    }
    __syncthreads();
    for (int i = threadIdx.x; i < C * NP; i += 256) {
        int cc = i / NP, k = i - cc * NP;
        smu8[cc * 8 + k] = __fdiv_rn(smu8[cc * 8 + k], rnorm[k]);
    }
    __syncthreads();

    float ms = g_msmall[g][n];
    float a[NP];
#pragma unroll
    for (int k = 0; k < NP; k++) a[k] = 0.0f;

    const float* fb = feat + n;
#pragma unroll 8
    for (int c = 0; c < C; c++) {                       // ascending c
        float x = __fmul_rn(ms, fb[(size_t)c * NN]);    // materialized x element
        float4 ma = *(const float4*)&smu8[c * 8];       // k = 0..3
        float  mb = smu8[c * 8 + 4];                    // k = 4
        a[0] = __fmaf_rn(x, ma.x, a[0]);
        a[1] = __fmaf_rn(x, ma.y, a[1]);
        a[2] = __fmaf_rn(x, ma.z, a[2]);
        a[3] = __fmaf_rn(x, ma.w, a[3]);
        a[4] = __fmaf_rn(x, mb,   a[4]);
    }

    if (simmode) {
#pragma unroll
        for (int k = 0; k < NP; k++) g_sim[g][k][n] = a[k];
        return;
    }

    float s[NP];
#pragma unroll
    for (int k = 0; k < NP; k++) s[k] = __fmul_rn(20.0f, a[k]);
    float mx = s[0];
#pragma unroll
    for (int k = 1; k < NP; k++) mx = fmaxf(mx, s[k]);
    float e[NP];
#pragma unroll
    for (int k = 0; k < NP; k++) e[k] = expf(__fadd_rn(s[k], -mx));
    float sum = e[0];
#pragma unroll
    for (int k = 1; k < NP; k++) sum = __fadd_rn(sum, e[k]);

    float zs[NP];
#pragma unroll
    for (int k = 0; k < NP; k++) {
        float z = __fdiv_rn(e[k], sum);                 // e / sum (IEEE divide)
        g_z[g][k][n] = z;
        zs[k] = z;
    }

    // deterministic colsum partials: shfl tree -> fixed 8-warp sum
    __shared__ float wpart[8][NP];
    int warp = threadIdx.x >> 5, lane = threadIdx.x & 31;
#pragma unroll
    for (int k = 0; k < NP; k++) {
        float t = zs[k];
        for (int o = 16; o > 0; o >>= 1) t += __shfl_down_sync(0xffffffffu, t, o);
        if (lane == 0) wpart[warp][k] = t;
    }
    __syncthreads();
    if (threadIdx.x < NP) {
        float ssum = 0.0f;
#pragma unroll
        for (int w = 0; w < 8; w++) ssum = __fadd_rn(ssum, wpart[w][threadIdx.x]);
        g_csum_part[g][b & 15][threadIdx.x] = ssum;
    }
}

// ---------------- mu numerator: R14 config (16 warps x 2 ch), unroll 4 ------
// grid = G*8 x 512 (16 warps x 2 channels = 32 channels/block; 8 blocks/g).
// Per-(c,k) FMA chain: n = t*2048 + it*128 + lane*4 ascending, groups of
// 4 FMAs in (x0,x1,x2,x3) order -> byte-identical to R7..R16 chains.
// unroll 4 only reschedules independent loads (deeper MLP vs L2 latency).
__global__ __launch_bounds__(512)
void k_mu(const float* __restrict__ feat) {
    int b = blockIdx.x;
    int g = b >> 3;
    int warp = threadIdx.x >> 5, lane = threadIdx.x & 31;
    int c0 = ((b & 7) << 5) + (warp << 1);          // 2 channels c0, c0+1

    __shared__ __align__(16) float zns[NP][2048];   // 40 KB
    __shared__ __align__(16) float msl[2048];       //  8 KB  (total 48 KB)

    float den[NP];
#pragma unroll
    for (int k = 0; k < NP; k++) {
        float s = 0.0f;
#pragma unroll
        for (int j = 0; j < 16; j++) s = __fadd_rn(s, g_csum_part[g][j][k]);
        den[k] = __fadd_rn(1e-6f, s);
    }

    float acc[2][NP];
#pragma unroll
    for (int cc = 0; cc < 2; cc++)
#pragma unroll
        for (int k = 0; k < NP; k++) acc[cc][k] = 0.0f;

    for (int t = 0; t < 2; t++) {
        if (t) __syncthreads();                     // previous tile consumed
        // stage ms (bit-copy) + zn (divide once, same values as old k_zn)
        for (int i = threadIdx.x; i < 512; i += 512)
            ((float4*)msl)[i] = __ldg((const float4*)(g_msmall[g] + t * 2048) + i);
        for (int i = threadIdx.x; i < NP * 512; i += 512) {
            int k = i >> 9, nn = i & 511;
            float4 zv = __ldg((const float4*)(g_z[g][k] + t * 2048) + nn);
            float4 o;
            o.x = __fdiv_rn(zv.x, den[k]);
            o.y = __fdiv_rn(zv.y, den[k]);
            o.z = __fdiv_rn(zv.z, den[k]);
            o.w = __fdiv_rn(zv.w, den[k]);
            ((float4*)zns[k])[nn] = o;
        }
        __syncthreads();

#pragma unroll 4
        for (int it = 0; it < 16; it++) {
            int nn = it * 128 + lane * 4;
            float4 m4 = *(const float4*)&msl[nn];
            float4 z4[NP];
#pragma unroll
            for (int k = 0; k < NP; k++) z4[k] = *(const float4*)&zns[k][nn];
#pragma unroll
            for (int cc = 0; cc < 2; cc++) {
                float4 f4 = __ldg((const float4*)(feat + (size_t)(c0 + cc) * NN
                                                  + t * 2048 + nn));
                float x0 = __fmul_rn(m4.x, f4.x);
                float x1 = __fmul_rn(m4.y, f4.y);
                float x2 = __fmul_rn(m4.z, f4.z);
                float x3 = __fmul_rn(m4.w, f4.w);
#pragma unroll
                for (int k = 0; k < NP; k++) {
                    acc[cc][k] = __fmaf_rn(x0, z4[k].x, acc[cc][k]);
                    acc[cc][k] = __fmaf_rn(x1, z4[k].y, acc[cc][k]);
                    acc[cc][k] = __fmaf_rn(x2, z4[k].z, acc[cc][k]);
                    acc[cc][k] = __fmaf_rn(x3, z4[k].w, acc[cc][k]);
                }
            }
        }
    }

    // identical 32-lane shuffle tree per (c,k)
#pragma unroll
    for (int cc = 0; cc < 2; cc++)
#pragma unroll
        for (int k = 0; k < NP; k++)
            for (int o = 16; o > 0; o >>= 1)
                acc[cc][k] += __shfl_down_sync(0xffffffffu, acc[cc][k], o);

    if (lane == 0) {
#pragma unroll
        for (int cc = 0; cc < 2; cc++)
#pragma unroll
            for (int k = 0; k < NP; k++)
                g_munum[g][c0 + cc][k] = acc[cc][k];
    }
}

// ---------------- final: upsample + assign + write + reductions -------------
__global__ __launch_bounds__(256)
void k_final(const int* __restrict__ fg, float* __restrict__ out) {
    int y = blockIdx.x, g = blockIdx.y;

    __shared__ float row[NP][64];
    float sy = (y + 0.5f) * 0.0625f - 0.5f;          // exact in f32
    sy = fminf(fmaxf(sy, 0.0f), 63.0f);
    int y0 = (int)sy; int y1 = min(y0 + 1, 63); float fy = sy - (float)y0;
    float wy0 = 1.0f - fy;

    for (int i = threadIdx.x; i < NP * 64; i += 256) {
        int k = i >> 6, xs = i & 63;
        float a = g_sim[g][k][y0 * 64 + xs];
        float bb = g_sim[g][k][y1 * 64 + xs];
        row[k][xs] = __fadd_rn(__fmul_rn(a, wy0), __fmul_rn(bb, fy));
    }
    __syncthreads();

    int xb = threadIdx.x << 2;
    int4 fg4 = *(const int4*)(fg + ((size_t)g * H + y) * W + xb);
    const int* fgv4 = &fg4.x;

    unsigned long long best[NP];
#pragma unroll
    for (int k = 0; k < NP; k++) best[k] = 0ull;
    int vb = 0;
    float ov[NP][4];

#pragma unroll
    for (int j = 0; j < 4; j++) {
        int x = xb + j;
        float sx = (x + 0.5f) * 0.0625f - 0.5f;
        sx = fminf(fmaxf(sx, 0.0f), 63.0f);
        int x0 = (int)sx; int x1 = min(x0 + 1, 63); float fx = sx - (float)x0;
        float wx0 = 1.0f - fx;

        float v[NP];
#pragma unroll
        for (int k = 0; k < NP; k++)
            v[k] = __fadd_rn(__fmul_rn(row[k][x0], wx0), __fmul_rn(row[k][x1], fx));

        int bk = 0; float bv = v[0];
#pragma unroll
        for (int k = 1; k < NP; k++) if (v[k] > bv) { bv = v[k]; bk = k; }

        int isfg = (fgv4[j] != 0);
        unsigned idx = (unsigned)(y * W + x);
#pragma unroll
        for (int k = 0; k < NP; k++) {
            float o = (isfg && k == bk) ? v[k] : 0.0f;
            ov[k][j] = o;
            unsigned long long key = pack_key(o, idx);
            if (key > best[k]) best[k] = key;
        }
        if (isfg) vb |= (1 << bk);
    }

#pragma unroll
    for (int k = 0; k < NP; k++) {
        float4 w4 = make_float4(ov[k][0], ov[k][1], ov[k][2], ov[k][3]);
        *(float4*)(out + ((((size_t)g * NP + k) * H + y) * W + xb)) = w4;
    }

#pragma unroll
    for (int k = 0; k < NP; k++)
        for (int o = 16; o > 0; o >>= 1) {
            unsigned long long other = __shfl_down_sync(0xffffffffu, best[k], o);
            if (other > best[k]) best[k] = other;
        }
    for (int o = 16; o > 0; o >>= 1) vb |= __shfl_down_sync(0xffffffffu, vb, o);

    __shared__ unsigned long long sb[8][NP];
    __shared__ int sv[8];
    int warp = threadIdx.x >> 5, lane = threadIdx.x & 31;
    if (lane == 0) {
#pragma unroll
        for (int k = 0; k < NP; k++) sb[warp][k] = best[k];
        sv[warp] = vb;
    }
    __syncthreads();
    if (threadIdx.x < NP) {
        int k = threadIdx.x;
        unsigned long long m = sb[0][k];
#pragma unroll
        for (int w = 1; w < 8; w++) if (sb[w][k] > m) m = sb[w][k];
        atomicMax(&g_best[g][k], m);
    }
    if (threadIdx.x == 0) {
        int o = 0;
#pragma unroll
        for (int w = 0; w < 8; w++) o |= sv[w];
        atomicOr(&g_visible[g], o);
    }
}

// ---------------- epilogue --------------------------------------------------
__global__ __launch_bounds__(128)
void k_points(float* __restrict__ out) {
    int t = threadIdx.x;
    if (t >= G * NP) return;
    int g = t / NP, k = t % NP;
    int vis = (g_visible[g] >> k) & 1;
    unsigned idx = 0xFFFFFFFFu - (unsigned)(g_best[g][k] & 0xFFFFFFFFull);
    float px = (float)(idx & (W - 1));
    float py = (float)(idx >> 10);
    size_t P = (size_t)G * NP * H * W;
    out[P + t * 2]     = vis ? px : -0.001f;
    out[P + t * 2 + 1] = vis ? py : -0.001f;
    out[P + (size_t)G * NP * 2 + t] = (float)vis;
}

// ---------------- launch ----------------------------------------------------
extern "C" void kernel_launch(void* const* d_in, const int* in_sizes, int n_in,
                              void* d_out, int out_size) {
    const float* feature = (const float*)d_in[0];   // (256,64,64)
    const int*   fg_mask = (const int*)d_in[1];     // (16,1024,1024)
    // d_in[2] = bboxes (unused by reference)
    const float* mu_in   = (const float*)d_in[3];   // (1,256,5)
    float* out = (float*)d_out;

    k_msmall<<<G * 16, 256>>>(fg_mask);
    k_init<<<1, 256>>>(mu_in);

    for (int it = 0; it < STAGES; it++) {
        k_logits<<<G * 16, 256>>>(feature, 0);
        k_mu<<<G * 8, 512>>>(feature);
    }
    k_logits<<<G * 16, 256>>>(feature, 1);   // sim = x^T mu_final

    k_final<<<dim3(H, G), 256>>>(fg_mask, out);
    k_points<<<1, 128>>>(out);
}